// round 10
// baseline (speedup 1.0000x reference)
#include <cuda_runtime.h>
#include <cstdint>

// Problem shape (fixed for this dataset entry)
#define B_ 4
#define C_ 32
#define H_ 256
#define W_ 512
#define D_ 48

#define WT   128            // w-tile per block
#define TW   (WT + D_)      // 176: h1 tile width, mult of 4 -> rows 16B-aligned
#define NTHREADS 256
#define CH_T 4              // channels per thread (warp wid owns 4*wid..4*wid+3)
#define W_T  4              // w outputs per thread (w0 = lane*4)
#define MROUNDS (D_ / 2)    // 24 mini-rounds of 2 d-steps

typedef unsigned long long ull;

// --- packed f32x2 helpers (FFMA2 is PTX-only; ptxas never auto-fuses) ---
__device__ __forceinline__ void fma2(ull &acc, ull a, ull b) {
    asm("fma.rn.f32x2 %0, %1, %2, %0;" : "+l"(acc) : "l"(a), "l"(b));
}
__device__ __forceinline__ ull pack2(float lo, float hi) {
    ull r;
    asm("mov.b64 %0, {%1, %2};" : "=l"(r) : "f"(lo), "f"(hi));
    return r;
}
__device__ __forceinline__ void unpack2(ull a, float &lo, float &hi) {
    asm("mov.b64 {%0, %1}, %2;" : "=f"(lo), "=f"(hi) : "l"(a));
}

__global__ void __launch_bounds__(NTHREADS, 3)
dense_warp_kernel(const float* __restrict__ h1,
                  const float* __restrict__ cost,
                  float* __restrict__ out) {
    __shared__ __align__(16) float cost_s[D_ * WT];   // 24 KB
    __shared__ __align__(16) float h1_s[C_ * TW];     // 22 KB

    const int bx    = blockIdx.x;
    const int wt    = bx & 3;                 // W_/WT = 4 tiles
    const int h     = (bx >> 2) & (H_ - 1);
    const int b     = bx >> 10;               // /(4*256)
    const int wbase = wt * WT;
    const int tid   = threadIdx.x;

    // ---- load cost tile [D_ x WT] (float4, coalesced): 1536 float4 ----
    {
        const float* cbase = cost + ((size_t)(b * D_) * H_ + h) * W_ + wbase;
        #pragma unroll
        for (int it = 0; it < 6; it++) {
            int idx = it * NTHREADS + tid;
            int dd = idx >> 5;               // WT/4 = 32 float4 per row
            int ww = (idx & 31) << 2;
            *(float4*)&cost_s[dd * WT + ww] =
                *(const float4*)&cbase[(size_t)dd * (H_ * W_) + ww];
        }
    }
    // ---- load h1 tile [C_ x TW] (float4), zero-padded past W ----
    // boundary W - wbase is a multiple of 4 -> whole-float4 guard is exact
    {
        const float* hbase = h1 + ((size_t)(b * C_) * H_ + h) * W_ + wbase;
        for (int idx = tid; idx < C_ * (TW / 4); idx += NTHREADS) {  // 1408
            int cc = idx / (TW / 4);
            int x  = (idx - cc * (TW / 4)) * 4;
            float4 v = make_float4(0.0f, 0.0f, 0.0f, 0.0f);
            if (wbase + x < W_)
                v = *(const float4*)&hbase[(size_t)cc * (H_ * W_) + x];
            *(float4*)&h1_s[cc * TW + x] = v;
        }
    }
    __syncthreads();

    // lane spans w (fully distinct smem reads, 512B contiguous per warp);
    // warp wid owns channels {4*wid .. 4*wid+3}, kept in registers.
    const int lane  = tid & 31;
    const int wid   = tid >> 5;               // 0..7
    const int w0    = lane * 4;               // 0..124
    const int cbch  = wid * 4;

    const float* hr0 = &h1_s[cbch * TW + w0]; // +i*TW per channel
    const float* cb  = &cost_s[w0];

    // Even-pair ring per channel.  Invariant at entry to mini-round m
    // (x_j = h1[w0+j]):  R[i][(m+k)&3] = (x_{2m+2k}, x_{2m+2k+1}), k=0..3
    ull R[CH_T][4], acc[CH_T][2];
    #pragma unroll
    for (int i = 0; i < CH_T; i++) {
        ulonglong2 a = *(const ulonglong2*)(hr0 + i * TW);      // x0..x3
        ulonglong2 c = *(const ulonglong2*)(hr0 + i * TW + 4);  // x4..x7
        R[i][0] = a.x; R[i][1] = a.y; R[i][2] = c.x; R[i][3] = c.y;
        acc[i][0] = 0ull; acc[i][1] = 0ull;
    }

    // Cost double-buffer: rows (2m, 2m+1) live in (qe, qo); next pair
    // prefetched at the top of each mini-round (load->use ~1 round).
    ulonglong2 qe = *(const ulonglong2*)(cb + 0 * WT);
    ulonglong2 qo = *(const ulonglong2*)(cb + 1 * WT);

    // 24 fully-unrolled mini-rounds of (even d=2m, odd d=2m+1).
    #pragma unroll
    for (int m = 0; m < MROUNDS; m++) {
        // prefetch next mini-round's cost rows (consumed at m+1)
        ulonglong2 qe_n = qe, qo_n = qo;
        if (m < MROUNDS - 1) {
            qe_n = *(const ulonglong2*)(cb + (2 * m + 2) * WT);
            qo_n = *(const ulonglong2*)(cb + (2 * m + 3) * WT);
        }
        // refill pairs (x_{2m+8}, x_{2m+9}) — first read at m+2
        ull nv[CH_T];
        if (m < MROUNDS - 2) {
            #pragma unroll
            for (int i = 0; i < CH_T; i++)
                nv[i] = *(const ull*)(hr0 + i * TW + 2 * m + 8);
        }

        #pragma unroll
        for (int i = 0; i < CH_T; i++) {
            ull P0 = R[i][(m + 0) & 3];   // (x_{2m},   x_{2m+1})
            ull P1 = R[i][(m + 1) & 3];   // (x_{2m+2}, x_{2m+3})
            ull P2 = R[i][(m + 2) & 3];   // (x_{2m+4}, x_{2m+5})

            float p0l, p0h, p1l, p1h, p2l, p2h;
            unpack2(P0, p0l, p0h);        // register aliasing, free
            unpack2(P1, p1l, p1h);
            unpack2(P2, p2l, p2h);
            ull O0 = pack2(p0h, p1l);     // (x_{2m+1}, x_{2m+2})
            ull O1 = pack2(p1h, p2l);     // (x_{2m+3}, x_{2m+4})

            // even d = 2m
            fma2(acc[i][0], qe.x, P0);
            fma2(acc[i][1], qe.y, P1);
            // odd d = 2m+1
            fma2(acc[i][0], qo.x, O0);
            fma2(acc[i][1], qo.y, O1);

            // retire slot P0, install lookahead pair
            if (m < MROUNDS - 2) R[i][m & 3] = nv[i];
        }
        qe = qe_n; qo = qo_n;
    }

    // ---- store: 4 channels x 4 contiguous floats (1x STG.128 each);
    //      warp stores 512B contiguous per channel ----
    #pragma unroll
    for (int i = 0; i < CH_T; i++) {
        int c = cbch + i;
        float* orow = out + (((size_t)b * C_ + c) * H_ + h) * W_ + wbase + w0;
        *(ulonglong2*)orow = make_ulonglong2(acc[i][0], acc[i][1]);
    }
}

extern "C" void kernel_launch(void* const* d_in, const int* in_sizes, int n_in,
                              void* d_out, int out_size) {
    (void)in_sizes; (void)n_in; (void)out_size;
    const float* h1   = (const float*)d_in[0];
    const float* cost = (const float*)d_in[1];
    float* out        = (float*)d_out;

    const int nblocks = B_ * H_ * (W_ / WT);   // 4096
    dense_warp_kernel<<<nblocks, NTHREADS>>>(h1, cost, out);
}

// round 12
// speedup vs baseline: 1.2518x; 1.2518x over previous
#include <cuda_runtime.h>
#include <cstdint>

// Problem shape (fixed for this dataset entry)
#define B_ 4
#define C_ 32
#define H_ 256
#define W_ 512
#define D_ 48

#define WT   128            // w-tile per block
#define TW   (WT + D_)      // 176: h1 tile width (window overhang)
#define TWP  178            // padded row stride (even, float2-aligned)
#define NTHREADS 256
#define CH_T 2              // channels per thread (stride 16)
#define W_T  8              // w outputs per thread
#define ROUNDS (D_ / 2)     // 24

typedef unsigned long long ull;

// --- packed f32x2 helpers (FFMA2 is PTX-only; ptxas never auto-fuses) ---
__device__ __forceinline__ void fma2(ull &acc, ull a, ull b) {
    asm("fma.rn.f32x2 %0, %1, %2, %0;" : "+l"(acc) : "l"(a), "l"(b));
}
__device__ __forceinline__ ull pack2(float lo, float hi) {
    ull r;
    asm("mov.b64 %0, {%1, %2};" : "=l"(r) : "f"(lo), "f"(hi));
    return r;
}
__device__ __forceinline__ void unpack2(ull a, float &lo, float &hi) {
    asm("mov.b64 {%0, %1}, %2;" : "=f"(lo), "=f"(hi) : "l"(a));
}

__global__ void __launch_bounds__(NTHREADS, 4)
dense_warp_kernel(const float* __restrict__ h1,
                  const float* __restrict__ cost,
                  float* __restrict__ out) {
    __shared__ __align__(16) float cost_s[D_ * WT];   // 24 KB
    __shared__ __align__(16) float h1_s[C_ * TWP];    // 22.8 KB

    const int bx    = blockIdx.x;
    const int wt    = bx & 3;                 // W_/WT = 4 tiles
    const int h     = (bx >> 2) & (H_ - 1);
    const int b     = bx >> 10;               // /(4*256)
    const int wbase = wt * WT;
    const int tid   = threadIdx.x;

    // ---- load cost tile [D_ x WT] (float4, coalesced): 1536 float4 ----
    {
        const float* cbase = cost + ((size_t)(b * D_) * H_ + h) * W_ + wbase;
        #pragma unroll
        for (int it = 0; it < 6; it++) {
            int idx = it * NTHREADS + tid;
            int dd = idx >> 5;               // WT/4 = 32 float4 per row
            int ww = (idx & 31) << 2;
            *(float4*)&cost_s[dd * WT + ww] =
                *(const float4*)&cbase[(size_t)dd * (H_ * W_) + ww];
        }
    }
    // ---- load h1 tile [C_ x TW] as float2, zero-padded past W ----
    {
        const float* hbase = h1 + ((size_t)(b * C_) * H_ + h) * W_ + wbase;
        #pragma unroll
        for (int it = 0; it < (C_ * (TW / 2)) / NTHREADS; it++) {   // 11 iters
            int idx = it * NTHREADS + tid;
            int cc = idx / (TW / 2);
            int x  = (idx - cc * (TW / 2)) * 2;
            float2 v = make_float2(0.0f, 0.0f);
            if (wbase + x < W_)
                v = *(const float2*)&hbase[(size_t)cc * (H_ * W_) + x];
            *(float2*)&h1_s[cc * TWP + x] = v;
        }
    }
    __syncthreads();

    // lane layout (R8, proven): c0 = lane&15, wsl = lane>>4
    // thread tile: channels {c0, c0+16} x w [w0, w0+8)
    const int lane = tid & 31;
    const int wid  = tid >> 5;                 // 0..7
    const int c0   = lane & 15;
    const int wsl  = lane >> 4;                // 0..1
    const int w0   = wid * 16 + wsl * 8;       // 0..120

    const float* hr = &h1_s[c0 * TWP + w0];    // + i*(16*TWP) per channel slot

    // E-only ring per channel.  Invariant at entry to round t (x_j = h1[w0+j]):
    //   E[i][(t+k)&3] = (x_{2t+2k}, x_{2t+2k+1}), k=0..3
    //   c8[i]         = x_{2t+8}
    // Odd-step operands derived per round:
    //   O_k = (E_k.hi, E_{k+1}.lo), k=0..2;  O_3 = (E_3.hi, c8)
    ull E[CH_T][4], acc[CH_T][4];
    float c8[CH_T];

    #pragma unroll
    for (int i = 0; i < CH_T; i++) {
        float f[9];
        #pragma unroll
        for (int j = 0; j < 9; j++) f[j] = hr[i * (16 * TWP) + j];
        E[i][0] = pack2(f[0], f[1]);
        E[i][1] = pack2(f[2], f[3]);
        E[i][2] = pack2(f[4], f[5]);
        E[i][3] = pack2(f[6], f[7]);
        c8[i]   = f[8];
        acc[i][0] = acc[i][1] = acc[i][2] = acc[i][3] = 0ull;
    }

    // Prefetch even-step cost for round 0 (d = 0).
    ulonglong2 qa = ((const ulonglong2*)&cost_s[0 * WT + w0])[0];
    ulonglong2 qb = ((const ulonglong2*)&cost_s[0 * WT + w0])[1];

    // 24 fully-unrolled rounds of (even d=2t, odd d=2t+1); static ring slots.
    // Even-step cost (qa,qb) was loaded one full round earlier.
    #pragma unroll
    for (int t = 0; t < ROUNDS; t++) {
        // issue this round's loads first (uses are ~15+ instrs away)
        float u[CH_T], v[CH_T];
        #pragma unroll
        for (int i = 0; i < CH_T; i++) {
            u[i] = hr[i * (16 * TWP) + 9  + 2 * t];   // x_{2t+9}
            v[i] = hr[i * (16 * TWP) + 10 + 2 * t];   // x_{2t+10}
        }
        const ulonglong2* cq = (const ulonglong2*)&cost_s[(2 * t + 1) * WT + w0];
        ulonglong2 r0 = cq[0], r1 = cq[1];

        // prefetch next round's even cost (dead-slot reuse on last round)
        const int nrow = (t < ROUNDS - 1) ? (2 * t + 2) : 0;
        const ulonglong2* cn = (const ulonglong2*)&cost_s[nrow * WT + w0];
        ulonglong2 n0 = cn[0], n1 = cn[1];

        #pragma unroll
        for (int i = 0; i < CH_T; i++) {
            ull E0 = E[i][(t + 0) & 3], E1 = E[i][(t + 1) & 3],
                E2 = E[i][(t + 2) & 3], E3 = E[i][(t + 3) & 3];

            // ---- even step d = 2t ----
            fma2(acc[i][0], qa.x, E0);
            fma2(acc[i][1], qa.y, E1);
            fma2(acc[i][2], qb.x, E2);
            fma2(acc[i][3], qb.y, E3);

            // derive odd operands (unpacks = register aliasing, free)
            float e0l, e0h, e1l, e1h, e2l, e2h, e3l, e3h;
            unpack2(E0, e0l, e0h); unpack2(E1, e1l, e1h);
            unpack2(E2, e2l, e2h); unpack2(E3, e3l, e3h);
            ull O0 = pack2(e0h, e1l);     // (x_{2t+1}, x_{2t+2})
            ull O1 = pack2(e1h, e2l);     // (x_{2t+3}, x_{2t+4})
            ull O2 = pack2(e2h, e3l);     // (x_{2t+5}, x_{2t+6})
            ull O3 = pack2(e3h, c8[i]);   // (x_{2t+7}, x_{2t+8})

            // ---- odd step d = 2t+1 ----
            fma2(acc[i][0], r0.x, O0);
            fma2(acc[i][1], r0.y, O1);
            fma2(acc[i][2], r1.x, O2);
            fma2(acc[i][3], r1.y, O3);

            // retire slot t&3, install (x_{2t+8}, x_{2t+9}); carry x_{2t+10}
            E[i][t & 3] = pack2(c8[i], u[i]);
            c8[i] = v[i];
        }
        qa = n0; qb = n1;
    }

    // ---- store: 2 channels x 8 contiguous floats (2x STG.128 each) ----
    #pragma unroll
    for (int i = 0; i < CH_T; i++) {
        int c = c0 + 16 * i;
        float* orow = out + (((size_t)b * C_ + c) * H_ + h) * W_ + wbase + w0;
        ulonglong2* ov = (ulonglong2*)orow;
        ov[0] = make_ulonglong2(acc[i][0], acc[i][1]);
        ov[1] = make_ulonglong2(acc[i][2], acc[i][3]);
    }
}

extern "C" void kernel_launch(void* const* d_in, const int* in_sizes, int n_in,
                              void* d_out, int out_size) {
    (void)in_sizes; (void)n_in; (void)out_size;
    const float* h1   = (const float*)d_in[0];
    const float* cost = (const float*)d_in[1];
    float* out        = (float*)d_out;

    const int nblocks = B_ * H_ * (W_ / WT);   // 4096
    dense_warp_kernel<<<nblocks, NTHREADS>>>(h1, cost, out);
}

// round 13
// speedup vs baseline: 1.4457x; 1.1549x over previous
#include <cuda_runtime.h>
#include <cstdint>

// Problem shape (fixed for this dataset entry)
#define B_  4
#define C_  32
#define H_  256
#define W_  512
#define D_  48
#define HW_ (H_ * W_)

#define WT  128              // w-tile per block
#define NTHREADS 256
#define MB  8                // m16-blocks per tile (one per warp)
#define KS  8                // k-steps (k8) per m-block: band 16+48 = 64 = 8*8
#define KCH 22               // distinct k8 chunks in window [0, 176)

// smem (dynamic): A-frag 8192 floats + B-frag 6336 floats = 58112 B
#define A_FLOATS 8192        // [MB][KS][32 lanes][4 slots]
#define B_FLOATS 6336        // [KCH][32 lanes][9] (8 used + 1 pad, stride 9)
#define SMEM_BYTES ((A_FLOATS + B_FLOATS) * 4)

// fp32 -> tf32 (round-to-nearest) kept in b32 register
__device__ __forceinline__ unsigned tf32_of(float v) {
    unsigned r;
    asm("cvt.rna.tf32.f32 %0, %1;" : "=r"(r) : "f"(v));
    return r;
}

// D(16x8,f32) += A(16x8,tf32,row) * B(8x8,tf32,col)
__device__ __forceinline__ void mma8(float* d,
                                     unsigned a0, unsigned a1,
                                     unsigned a2, unsigned a3,
                                     unsigned b0, unsigned b1) {
    asm volatile(
        "mma.sync.aligned.m16n8k8.row.col.f32.tf32.tf32.f32 "
        "{%0,%1,%2,%3}, {%4,%5,%6,%7}, {%8,%9}, {%0,%1,%2,%3};"
        : "+f"(d[0]), "+f"(d[1]), "+f"(d[2]), "+f"(d[3])
        : "r"(a0), "r"(a1), "r"(a2), "r"(a3), "r"(b0), "r"(b1));
}

__global__ void __launch_bounds__(NTHREADS)
dense_warp_kernel(const float* __restrict__ h1,
                  const float* __restrict__ cost,
                  float* __restrict__ out) {
    extern __shared__ __align__(16) unsigned smu[];
    unsigned* Af = smu;                // A-frag region
    unsigned* Bf = smu + A_FLOATS;     // B-frag region

    const int bx    = blockIdx.x;
    const int wt    = bx & 3;                 // W_/WT = 4 tiles
    const int h     = (bx >> 2) & (H_ - 1);
    const int b     = bx >> 10;               // /(4*256)
    const int wbase = wt * WT;
    const int tid   = threadIdx.x;

    const float* cbase = cost + ((size_t)(b * D_) * H_ + h) * W_ + wbase;
    const float* hbase = h1   + ((size_t)(b * C_) * H_ + h) * W_ + wbase;

    // ---- 1. zero A (covers out-of-band slots) ----
    {
        uint4 z = make_uint4(0u, 0u, 0u, 0u);
        #pragma unroll
        for (int i = 0; i < A_FLOATS / 4 / NTHREADS; i++)     // 8 iters
            ((uint4*)Af)[i * NTHREADS + tid] = z;
    }
    __syncthreads();

    // ---- 2. A band fill ----
    // A-block[mb][jj][kk] = tf32(cost[d][wbase + 16*mb + jj]), kk = jj + d.
    // d<=47, jj<=15 -> kk<=62 always in [0,64): every (jj,d) lands in-band.
    // frag scatter: g=jj&7, hi=jj>>3, ks=kk>>3, t=kk&3, bit2=(kk>>2)&1
    //   addr = ((mb*8+ks)*32 + g*4+t)*4 + hi + 2*bit2
    {
        const int seg = tid >> 4;            // 0..15
        const int jj  = tid & 15;
        #pragma unroll
        for (int i = 0; i < (MB * D_) / 16; i++) {            // 24 iters
            int task = i * 16 + seg;         // 0..383
            int mb   = task / D_;
            int d    = task - mb * D_;
            unsigned v = tf32_of(cbase[(size_t)d * HW_ + mb * 16 + jj]);
            int kk = jj + d;                 // 0..62
            int ks = kk >> 3, t = kk & 3, bit2 = (kk >> 2) & 1;
            int g  = jj & 7,  hi = jj >> 3;
            Af[(((mb * 8 + ks) * 32) + g * 4 + t) * 4 + hi + 2 * bit2] = v;
        }
    }

    // ---- 3. B fill ----
    // B[k][c] = tf32(h1[c][wbase+k]) (0 beyond W), k in [0,176), c in [0,32)
    // frag scatter: ch=k>>3, r=k&7, t=r&3, j=r>>2, g=c&7, nt=c>>3
    //   addr = ch*288 + (g*4+t)*9 + 2*nt + j
    {
        #pragma unroll
        for (int i = 0; i < (C_ * 176) / NTHREADS; i++) {     // 22 iters
            int idx = i * NTHREADS + tid;    // 0..5631
            int c = idx / 176;
            int k = idx - c * 176;
            float fv = (wbase + k < W_) ? hbase[(size_t)c * HW_ + k] : 0.0f;
            unsigned v = tf32_of(fv);
            int ch = k >> 3, r = k & 7, t = r & 3, j = r >> 2;
            int g  = c & 7,  nt = c >> 3;
            Bf[ch * 288 + (g * 4 + t) * 9 + 2 * nt + j] = v;
        }
    }
    __syncthreads();

    // ---- 4. mainloop: warp wid owns m-block wid (w rows 16*wid..+15) ----
    const int lane = tid & 31;
    const int wid  = tid >> 5;               // 0..7

    float acc[16];
    #pragma unroll
    for (int i = 0; i < 16; i++) acc[i] = 0.0f;

    const uint4*    Ald = (const uint4*)Af + (wid * 8) * 32 + lane;
    const unsigned* Bld = Bf + lane * 9;

    #pragma unroll
    for (int ks = 0; ks < KS; ks++) {
        uint4 a = Ald[ks * 32];                          // LDS.128, lane-major
        const unsigned* bp = Bld + (2 * wid + ks) * 288; // chunk = kbase/8
        #pragma unroll
        for (int nt = 0; nt < 4; nt++) {
            unsigned b0 = bp[2 * nt + 0];
            unsigned b1 = bp[2 * nt + 1];
            mma8(acc + nt * 4, a.x, a.y, a.z, a.w, b0, b1);
        }
    }

    // ---- 5. epilogue: D[g][2t] layout -> out[c][w] scatter ----
    // d0:(w=+g, c), d1:(+g, c+1), d2:(+g+8, c), d3:(+g+8, c+1)
    {
        const int g = lane >> 2, t = lane & 3;
        const int w = wbase + wid * 16 + g;
        float* obase = out + ((size_t)(b * C_) * H_ + h) * W_;
        #pragma unroll
        for (int nt = 0; nt < 4; nt++) {
            int c = nt * 8 + t * 2;
            float* p = obase + (size_t)c * HW_ + w;
            p[0]       = acc[nt * 4 + 0];
            p[HW_]     = acc[nt * 4 + 1];
            p[8]       = acc[nt * 4 + 2];
            p[HW_ + 8] = acc[nt * 4 + 3];
        }
    }
}

extern "C" void kernel_launch(void* const* d_in, const int* in_sizes, int n_in,
                              void* d_out, int out_size) {
    (void)in_sizes; (void)n_in; (void)out_size;
    const float* h1   = (const float*)d_in[0];
    const float* cost = (const float*)d_in[1];
    float* out        = (float*)d_out;

    // >48KB static limit -> dynamic smem (attribute set is idempotent,
    // not a stream op, and performs no allocation)
    cudaFuncSetAttribute(dense_warp_kernel,
                         cudaFuncAttributeMaxDynamicSharedMemorySize,
                         SMEM_BYTES);

    const int nblocks = B_ * H_ * (W_ / WT);   // 4096
    dense_warp_kernel<<<nblocks, NTHREADS, SMEM_BYTES>>>(h1, cost, out);
}